// round 1
// baseline (speedup 1.0000x reference)
#include <cuda_runtime.h>
#include <cstdint>

// ---------------------------------------------------------------------------
// Problem constants
// ---------------------------------------------------------------------------
#define BATCH   16384
#define D_IN    256
#define D_H     512
#define NQ      12
#define NLAYERS 4
#define FULLM   0xffffffffu

// Scratch for h = relu(data @ W_graph + b_graph): 16384 x 512 fp32 = 32 MB
__device__ float g_h[(size_t)BATCH * D_H];

// ---------------------------------------------------------------------------
// Compile-time helpers for the deferred Gray-code register permutation.
// D(r) = r ^ (r>>1)  (binary->gray map on 7 bits).  Phi_e = D^e.
// E = D^{-1} (gray decode / prefix-xor).
// ---------------------------------------------------------------------------
__host__ __device__ constexpr int D1(int r) { return (r ^ (r >> 1)) & 127; }
__host__ __device__ constexpr int E1(int y) {
    int x = y & 127;
    x ^= x >> 1;
    x ^= x >> 2;
    x ^= x >> 4;
    return x & 127;
}
__host__ __device__ constexpr int Dn(int r, int e) {
    for (int i = 0; i < e; i++) r = D1(r);
    return r;
}
__host__ __device__ constexpr int En(int p, int e) {
    for (int i = 0; i < e; i++) p = E1(p);
    return p;
}
__host__ __device__ constexpr int cpop(int v) {
    int c = 0;
    for (int i = 0; i < 12; i++) c += (v >> i) & 1;
    return c;
}

// ---------------------------------------------------------------------------
// Kernel 1: h = relu(data @ W_graph + b_graph)
// Classic 128x128x8 SIMT SGEMM, 256 threads, 8x8 microtile.
// ---------------------------------------------------------------------------
__global__ void __launch_bounds__(256)
gemm_relu_kernel(const float* __restrict__ A,     // [BATCH, D_IN]
                 const float* __restrict__ B,     // [D_IN, D_H]
                 const float* __restrict__ bias)  // [D_H]
{
    __shared__ float As[8][128];
    __shared__ float Bs[8][128];

    const int tid = threadIdx.x;
    const int colBase = blockIdx.x * 128;   // 0..3  -> N
    const int rowBase = blockIdx.y * 128;   // 0..127 -> M

    const int innerRowA = tid >> 1;          // 0..127
    const int innerColA = (tid & 1) * 4;     // 0 or 4
    const int innerRowB = tid >> 5;          // 0..7
    const int innerColB = (tid & 31) * 4;    // 0..124

    const int tr = (tid >> 4) * 8;           // 0..120
    const int tc = (tid & 15) * 8;           // 0..120

    float acc[8][8];
#pragma unroll
    for (int i = 0; i < 8; i++)
#pragma unroll
        for (int j = 0; j < 8; j++) acc[i][j] = 0.f;

    const float* Aptr = A + (size_t)(rowBase + innerRowA) * D_IN + innerColA;
    const float* Bptr = B + (size_t)innerRowB * D_H + colBase + innerColB;

    for (int k0 = 0; k0 < D_IN; k0 += 8) {
        float4 av = *reinterpret_cast<const float4*>(Aptr + k0);
        float4 bv = *reinterpret_cast<const float4*>(Bptr + (size_t)k0 * D_H);

        As[innerColA + 0][innerRowA] = av.x;
        As[innerColA + 1][innerRowA] = av.y;
        As[innerColA + 2][innerRowA] = av.z;
        As[innerColA + 3][innerRowA] = av.w;
        *reinterpret_cast<float4*>(&Bs[innerRowB][innerColB]) = bv;
        __syncthreads();

#pragma unroll
        for (int kk = 0; kk < 8; kk++) {
            float ra[8], rb[8];
            float4 a0 = *reinterpret_cast<const float4*>(&As[kk][tr]);
            float4 a1 = *reinterpret_cast<const float4*>(&As[kk][tr + 4]);
            float4 b0 = *reinterpret_cast<const float4*>(&Bs[kk][tc]);
            float4 b1 = *reinterpret_cast<const float4*>(&Bs[kk][tc + 4]);
            ra[0] = a0.x; ra[1] = a0.y; ra[2] = a0.z; ra[3] = a0.w;
            ra[4] = a1.x; ra[5] = a1.y; ra[6] = a1.z; ra[7] = a1.w;
            rb[0] = b0.x; rb[1] = b0.y; rb[2] = b0.z; rb[3] = b0.w;
            rb[4] = b1.x; rb[5] = b1.y; rb[6] = b1.z; rb[7] = b1.w;
#pragma unroll
            for (int i = 0; i < 8; i++)
#pragma unroll
                for (int j = 0; j < 8; j++)
                    acc[i][j] = fmaf(ra[i], rb[j], acc[i][j]);
        }
        __syncthreads();
    }

#pragma unroll
    for (int i = 0; i < 8; i++) {
        const int row = rowBase + tr + i;
#pragma unroll
        for (int j = 0; j < 8; j += 4) {
            const int col = colBase + tc + j;
            float4 v;
            v.x = fmaxf(acc[i][j + 0] + bias[col + 0], 0.f);
            v.y = fmaxf(acc[i][j + 1] + bias[col + 1], 0.f);
            v.z = fmaxf(acc[i][j + 2] + bias[col + 2], 0.f);
            v.w = fmaxf(acc[i][j + 3] + bias[col + 3], 0.f);
            *reinterpret_cast<float4*>(&g_h[(size_t)row * D_H + col]) = v;
        }
    }
}

// ---------------------------------------------------------------------------
// Kernel 2: fused  x = h @ W_pre + b_pre  ->  12-qubit sim  ->  expectation.
// One warp per sample; state (4096 fp32) lives in registers: st[128] per lane.
// Logical amplitude index m = (R<<5)|lane, R = 7-bit register part.
// Wire w acts on logical bit (11-w):  bits 11..5 -> register part,
// bits 4..0 -> lane part (shfl_xor).
// Per-layer CNOT chain == st'[m] = st[m ^ (m>>1)].  The register part of
// this permutation is deferred symbolically (Phi_e = D^e); only the lane
// part is performed physically (one in-place shfl per register).
// ---------------------------------------------------------------------------
__global__ void __launch_bounds__(128)
sim_kernel(const float* __restrict__ Wp,   // [D_H, NQ]
           const float* __restrict__ bp,   // [NQ]
           const float* __restrict__ qw,   // [NLAYERS*NQ]
           float* __restrict__ out)        // [BATCH]
{
    __shared__ float qc[NLAYERS * NQ];
    __shared__ float qs[NLAYERS * NQ];
    const int tid = threadIdx.x;
    if (tid < NLAYERS * NQ) {
        float a = qw[tid] * 0.5f;
        qc[tid] = cosf(a);
        qs[tid] = sinf(a);
    }
    __syncthreads();

    const int lane = tid & 31;
    const int warp = tid >> 5;
    const int s = blockIdx.x * 4 + warp;
    const float* hr = g_h + (size_t)s * D_H;

    // ---- x = h_row @ W_pre + b_pre (warp-cooperative) ----
    float xa[NQ];
#pragma unroll
    for (int q = 0; q < NQ; q++) xa[q] = 0.f;

#pragma unroll
    for (int j = 0; j < 16; j++) {
        const int k = lane + 32 * j;
        const float hv = hr[k];
        const float4* wrow = reinterpret_cast<const float4*>(Wp + (size_t)k * NQ);
        float4 w0 = wrow[0], w1 = wrow[1], w2 = wrow[2];
        xa[0]  = fmaf(hv, w0.x, xa[0]);
        xa[1]  = fmaf(hv, w0.y, xa[1]);
        xa[2]  = fmaf(hv, w0.z, xa[2]);
        xa[3]  = fmaf(hv, w0.w, xa[3]);
        xa[4]  = fmaf(hv, w1.x, xa[4]);
        xa[5]  = fmaf(hv, w1.y, xa[5]);
        xa[6]  = fmaf(hv, w1.z, xa[6]);
        xa[7]  = fmaf(hv, w1.w, xa[7]);
        xa[8]  = fmaf(hv, w2.x, xa[8]);
        xa[9]  = fmaf(hv, w2.y, xa[9]);
        xa[10] = fmaf(hv, w2.z, xa[10]);
        xa[11] = fmaf(hv, w2.w, xa[11]);
    }

    // butterfly-reduce each of the 12 sums; lane q keeps x_q
    float myx = 0.f;
#pragma unroll
    for (int q = 0; q < NQ; q++) {
        float v = xa[q];
#pragma unroll
        for (int o = 16; o; o >>= 1) v += __shfl_xor_sync(FULLM, v, o);
        if (lane == q) myx = v + bp[q];
    }

    // theta = atan(x) + pi/2 ; need cos(theta/2), sin(theta/2)
    const float half = fmaf(0.5f, atanf(myx), 0.78539816339744831f);
    float ms, mc;
    sincosf(half, &ms, &mc);

    float c0[NQ], s0[NQ];
#pragma unroll
    for (int w = 0; w < NQ; w++) {
        c0[w] = __shfl_sync(FULLM, mc, w);
        s0[w] = __shfl_sync(FULLM, ms, w);
    }

    // ---- build initial product state directly ----
    // lane bit b corresponds to wire 11-b; register bit t to wire 6-t
    float st[128];
    {
        float plo = ((lane >> 0) & 1) ? s0[11] : c0[11];
        plo *= ((lane >> 1) & 1) ? s0[10] : c0[10];
        plo *= ((lane >> 2) & 1) ? s0[9]  : c0[9];
        plo *= ((lane >> 3) & 1) ? s0[8]  : c0[8];
        plo *= ((lane >> 4) & 1) ? s0[7]  : c0[7];
        st[0] = plo;
#pragma unroll
        for (int t = 0; t < 7; t++) {
            const float cf = c0[6 - t];
            const float sf = s0[6 - t];
#pragma unroll
            for (int r = 0; r < (1 << t); r++) {
                st[r | (1 << t)] = st[r] * sf;
                st[r] = st[r] * cf;
            }
        }
    }

    // ---- layers ----
    const int grayLane = lane ^ (lane >> 1);
#pragma unroll
    for (int ell = 0; ell < NLAYERS; ell++) {
#pragma unroll
        for (int w = 0; w < NQ; w++) {
            const float cc = qc[ell * NQ + w];
            const float sv = qs[ell * NQ + w];
            if (w < 7) {
                // register-bit RY, logical reg bit bt = 6-w, in deferred frame
                const int bt = 6 - w;
                const int M = Dn(1 << bt, ell);   // physical pair mask
#pragma unroll
                for (int p = 0; p < 128; p++) {
                    if (((En(p, ell) >> bt) & 1) == 0) {
                        const float a = st[p];
                        const float b = st[p ^ M];
                        st[p]     = fmaf(cc, a, -sv * b);
                        st[p ^ M] = fmaf(sv, a,  cc * b);
                    }
                }
            } else {
                // lane-bit RY (wires 7..11 -> lane bit 11-w)
                const int b = 11 - w;
                const float sg = ((lane >> b) & 1) ? sv : -sv;
#pragma unroll
                for (int p = 0; p < 128; p++) {
                    const float part = __shfl_xor_sync(FULLM, st[p], 1 << b);
                    st[p] = fmaf(sg, part, cc * st[p]);
                }
            }
        }
        // CNOT chain == gray permutation; register part deferred, lane part
        // physical: st[p] <- st[p] from lane gray(lane) ^ (c_p<<4),
        // c_p = bit0 of the new-epoch logical reg index E^{ell+1}(p).
#pragma unroll
        for (int p = 0; p < 128; p++) {
            const int cp = En(p, ell + 1) & 1;
            const int sl = grayLane ^ (cp << 4);
            st[p] = __shfl_sync(FULLM, st[p], sl);
        }
    }

    // ---- measurement:  sum st^2 * (12 - 2*popc(m)),
    //      m = (E^4(p)<<5) | lane  ----
    float acc1 = 0.f, acc2 = 0.f;
#pragma unroll
    for (int p = 0; p < 128; p++) {
        const float Kp = (float)(NQ - 2 * cpop(En(p, NLAYERS)));
        const float t = st[p] * st[p];
        acc1 = fmaf(t, Kp, acc1);
        acc2 += t;
    }
    float res = fmaf(-2.0f * (float)__popc(lane), acc2, acc1);
#pragma unroll
    for (int o = 16; o; o >>= 1) res += __shfl_xor_sync(FULLM, res, o);
    if (lane == 0) out[s] = res;
}

// ---------------------------------------------------------------------------
extern "C" void kernel_launch(void* const* d_in, const int* in_sizes, int n_in,
                              void* d_out, int out_size)
{
    const float* data = (const float*)d_in[0];
    const float* Wg   = (const float*)d_in[1];
    const float* bg   = (const float*)d_in[2];
    const float* Wp   = (const float*)d_in[3];
    const float* bp   = (const float*)d_in[4];
    const float* qw   = (const float*)d_in[5];
    float* out = (float*)d_out;

    dim3 gGrid(D_H / 128, BATCH / 128);
    gemm_relu_kernel<<<gGrid, 256>>>(data, Wg, bg);

    sim_kernel<<<BATCH / 4, 128>>>(Wp, bp, qw, out);
}

// round 2
// speedup vs baseline: 6.0644x; 6.0644x over previous
#include <cuda_runtime.h>
#include <cstdint>

// ---------------------------------------------------------------------------
#define BATCH   16384
#define D_IN    256
#define D_H     512
#define NQ      12
#define NLAYERS 4
#define FULLM   0xffffffffu

// Scratch for h = relu(data @ W_graph + b_graph): 16384 x 512 fp32 = 32 MB
__device__ float g_h[(size_t)BATCH * D_H];

__host__ __device__ constexpr int cpop(int v) {
    int c = 0;
    for (int i = 0; i < 12; i++) c += (v >> i) & 1;
    return c;
}

// ---------------------------------------------------------------------------
// Kernel 1: h = relu(data @ W_graph + b_graph)
// 128x128x8 SIMT SGEMM, 256 threads, 8x8 microtile. (unchanged from R1)
// ---------------------------------------------------------------------------
__global__ void __launch_bounds__(256)
gemm_relu_kernel(const float* __restrict__ A,
                 const float* __restrict__ B,
                 const float* __restrict__ bias)
{
    __shared__ float As[8][128];
    __shared__ float Bs[8][128];

    const int tid = threadIdx.x;
    const int colBase = blockIdx.x * 128;
    const int rowBase = blockIdx.y * 128;

    const int innerRowA = tid >> 1;
    const int innerColA = (tid & 1) * 4;
    const int innerRowB = tid >> 5;
    const int innerColB = (tid & 31) * 4;

    const int tr = (tid >> 4) * 8;
    const int tc = (tid & 15) * 8;

    float acc[8][8];
#pragma unroll
    for (int i = 0; i < 8; i++)
#pragma unroll
        for (int j = 0; j < 8; j++) acc[i][j] = 0.f;

    const float* Aptr = A + (size_t)(rowBase + innerRowA) * D_IN + innerColA;
    const float* Bptr = B + (size_t)innerRowB * D_H + colBase + innerColB;

    for (int k0 = 0; k0 < D_IN; k0 += 8) {
        float4 av = *reinterpret_cast<const float4*>(Aptr + k0);
        float4 bv = *reinterpret_cast<const float4*>(Bptr + (size_t)k0 * D_H);

        As[innerColA + 0][innerRowA] = av.x;
        As[innerColA + 1][innerRowA] = av.y;
        As[innerColA + 2][innerRowA] = av.z;
        As[innerColA + 3][innerRowA] = av.w;
        *reinterpret_cast<float4*>(&Bs[innerRowB][innerColB]) = bv;
        __syncthreads();

#pragma unroll
        for (int kk = 0; kk < 8; kk++) {
            float ra[8], rb[8];
            float4 a0 = *reinterpret_cast<const float4*>(&As[kk][tr]);
            float4 a1 = *reinterpret_cast<const float4*>(&As[kk][tr + 4]);
            float4 b0 = *reinterpret_cast<const float4*>(&Bs[kk][tc]);
            float4 b1 = *reinterpret_cast<const float4*>(&Bs[kk][tc + 4]);
            ra[0] = a0.x; ra[1] = a0.y; ra[2] = a0.z; ra[3] = a0.w;
            ra[4] = a1.x; ra[5] = a1.y; ra[6] = a1.z; ra[7] = a1.w;
            rb[0] = b0.x; rb[1] = b0.y; rb[2] = b0.z; rb[3] = b0.w;
            rb[4] = b1.x; rb[5] = b1.y; rb[6] = b1.z; rb[7] = b1.w;
#pragma unroll
            for (int i = 0; i < 8; i++)
#pragma unroll
                for (int j = 0; j < 8; j++)
                    acc[i][j] = fmaf(ra[i], rb[j], acc[i][j]);
        }
        __syncthreads();
    }

#pragma unroll
    for (int i = 0; i < 8; i++) {
        const int row = rowBase + tr + i;
#pragma unroll
        for (int j = 0; j < 8; j += 4) {
            const int col = colBase + tc + j;
            float4 v;
            v.x = fmaxf(acc[i][j + 0] + bias[col + 0], 0.f);
            v.y = fmaxf(acc[i][j + 1] + bias[col + 1], 0.f);
            v.z = fmaxf(acc[i][j + 2] + bias[col + 2], 0.f);
            v.w = fmaxf(acc[i][j + 3] + bias[col + 3], 0.f);
            *reinterpret_cast<float4*>(&g_h[(size_t)row * D_H + col]) = v;
        }
    }
}

// ---------------------------------------------------------------------------
// Kernel 2: fused x = h @ W_pre + b_pre -> 12-qubit sim -> expectation.
//
// 2 warps per sample, 64 state floats per lane (no spills).
// Layout A: amp index m = (r<<6)|(wp<<5)|lane
//           reg bit t = logical bit 6+t (wires 0..5), wp = logical bit 5
//           (wire 6), lane bit b = logical bit b (wires 7..11).
// Layout B: m = ((r>>5)<<11)|(lane<<6)|(wp<<5)|(r&31)
//           reg bits 4..0 = logical bits 4..0 (wires 7..11).
// Per layer: wires0-5 (reg FMA, A) -> smem transpose A->B -> wires7-11
// (reg FMA, B) -> one smem trip doing wire6 + CNOT gray perm + B->A.
// RY in tan-form (2 FMA/pair); all 48 cos factors folded into the initial
// amplitude. Smem swizzle addr = m ^ ((m>>6)&31) is bank-conflict-free in
// every phase.
// ---------------------------------------------------------------------------
__global__ void __launch_bounds__(128)
sim_kernel(const float* __restrict__ Wp,   // [D_H, NQ]
           const float* __restrict__ bp,   // [NQ]
           const float* __restrict__ qw,   // [NLAYERS*NQ]
           float* __restrict__ out)        // [BATCH]
{
    __shared__ float stb[2][4096];
    __shared__ float qt[NLAYERS * NQ];
    __shared__ float qcc[NLAYERS * NQ];
    __shared__ float cS[2][NQ], sS[2][NQ];
    __shared__ float xpart[2][2][NQ];
    __shared__ float Cfold;

    const int tid = threadIdx.x;
    if (tid < NLAYERS * NQ) {
        float a = qw[tid] * 0.5f;
        float sv, cv;
        sincosf(a, &sv, &cv);
        qt[tid]  = sv / cv;
        qcc[tid] = cv;
    }
    __syncthreads();
    if (tid == 0) {
        float C = 1.f;
#pragma unroll
        for (int i = 0; i < NLAYERS * NQ; i++) C *= qcc[i];
        Cfold = C;
    }

    const int sb   = tid >> 6;          // sample within block (0/1)
    const int wp   = (tid >> 5) & 1;    // warp within sample
    const int lane = tid & 31;
    const int s = blockIdx.x * 2 + sb;
    const float* hr = g_h + (size_t)s * D_H;

    // ---- x = h_row @ W_pre + b_pre (two warps split the K range) ----
    float xa[NQ];
#pragma unroll
    for (int q = 0; q < NQ; q++) xa[q] = 0.f;
#pragma unroll
    for (int j = 0; j < 8; j++) {
        const int k = wp * 256 + j * 32 + lane;
        const float hv = hr[k];
        const float4* wr = reinterpret_cast<const float4*>(Wp + (size_t)k * NQ);
        float4 w0 = wr[0], w1 = wr[1], w2 = wr[2];
        xa[0]  = fmaf(hv, w0.x, xa[0]);
        xa[1]  = fmaf(hv, w0.y, xa[1]);
        xa[2]  = fmaf(hv, w0.z, xa[2]);
        xa[3]  = fmaf(hv, w0.w, xa[3]);
        xa[4]  = fmaf(hv, w1.x, xa[4]);
        xa[5]  = fmaf(hv, w1.y, xa[5]);
        xa[6]  = fmaf(hv, w1.z, xa[6]);
        xa[7]  = fmaf(hv, w1.w, xa[7]);
        xa[8]  = fmaf(hv, w2.x, xa[8]);
        xa[9]  = fmaf(hv, w2.y, xa[9]);
        xa[10] = fmaf(hv, w2.z, xa[10]);
        xa[11] = fmaf(hv, w2.w, xa[11]);
    }
#pragma unroll
    for (int q = 0; q < NQ; q++) {
        float v = xa[q];
#pragma unroll
        for (int o = 16; o; o >>= 1) v += __shfl_xor_sync(FULLM, v, o);
        if (lane == q) xpart[sb][wp][q] = v;
    }
    __syncthreads();
    if (wp == 0 && lane < NQ) {
        float x = xpart[sb][0][lane] + xpart[sb][1][lane] + bp[lane];
        float half = fmaf(0.5f, atanf(x), 0.78539816339744831f);
        float sv, cv;
        sincosf(half, &sv, &cv);
        cS[sb][lane] = cv;
        sS[sb][lane] = sv;
    }
    __syncthreads();

    // ---- initial product state (layout A) ----
    // wire w in 7..11 <-> lane bit 11-w ; wire 6 <-> wp ; wire w in 0..5 <-> reg bit 5-w
    float base = ((lane >> 4) & 1) ? sS[sb][7]  : cS[sb][7];
    base *= ((lane >> 3) & 1) ? sS[sb][8]  : cS[sb][8];
    base *= ((lane >> 2) & 1) ? sS[sb][9]  : cS[sb][9];
    base *= ((lane >> 1) & 1) ? sS[sb][10] : cS[sb][10];
    base *= ((lane >> 0) & 1) ? sS[sb][11] : cS[sb][11];
    base *= wp ? sS[sb][6] : cS[sb][6];
    base *= Cfold;

    float st[64];
    st[0] = base;
#pragma unroll
    for (int tb = 0; tb < 6; tb++) {
        const float cf = cS[sb][5 - tb];
        const float sf = sS[sb][5 - tb];
#pragma unroll
        for (int r = 0; r < (1 << tb); r++) {
            st[r | (1 << tb)] = st[r] * sf;
            st[r] = st[r] * cf;
        }
    }

    // ---- layers (ell loop NOT unrolled to keep I-footprint small) ----
#pragma unroll 1
    for (int ell = 0; ell < NLAYERS; ell++) {
        const int qb = ell * NQ;
        // wires 0..5 : reg bit 5-w, tan-form pairs
#pragma unroll
        for (int w = 0; w < 6; w++) {
            const float tt = qt[qb + w];
            const int bt = 5 - w;
#pragma unroll
            for (int r = 0; r < 64; r++) {
                if (((r >> bt) & 1) == 0) {
                    const int r2 = r | (1 << bt);
                    const float a = st[r];
                    const float b = st[r2];
                    st[r]  = fmaf(-tt, b, a);
                    st[r2] = fmaf(tt, a, b);
                }
            }
        }

        // transpose A -> B through smem (swizzled, conflict-free)
        __syncthreads();
#pragma unroll
        for (int r = 0; r < 64; r++) {
            const int m = (r << 6) | (wp << 5) | lane;
            stb[sb][m ^ ((m >> 6) & 31)] = st[r];
        }
        __syncthreads();
#pragma unroll
        for (int r = 0; r < 64; r++) {
            const int m = ((r >> 5) << 11) | (lane << 6) | (wp << 5) | (r & 31);
            st[r] = stb[sb][m ^ ((m >> 6) & 31)];
        }

        // wires 7..11 : layout-B reg bit 11-w
#pragma unroll
        for (int w = 7; w < 12; w++) {
            const float tt = qt[qb + w];
            const int bt = 11 - w;
#pragma unroll
            for (int r = 0; r < 64; r++) {
                if (((r >> bt) & 1) == 0) {
                    const int r2 = r | (1 << bt);
                    const float a = st[r];
                    const float b = st[r2];
                    st[r]  = fmaf(-tt, b, a);
                    st[r2] = fmaf(tt, a, b);
                }
            }
        }

        // trip 2: wire6 (warp bit) + CNOT gray permutation + transpose B -> A
        __syncthreads();
#pragma unroll
        for (int r = 0; r < 64; r++) {
            const int m = ((r >> 5) << 11) | (lane << 6) | (wp << 5) | (r & 31);
            stb[sb][m ^ ((m >> 6) & 31)] = st[r];
        }
        __syncthreads();
        const float t6 = qt[qb + 6];
#pragma unroll
        for (int r = 0; r < 64; r++) {
            const int m = (r << 6) | (wp << 5) | lane;
            const int q = m ^ (m >> 1);
            const int addr = q ^ ((q >> 6) & 31);
            const float v0 = stb[sb][addr];
            const float v1 = stb[sb][addr ^ 32];
            // q bit5 = wp ^ (r&1) selects the RY sign for wire 6
            const float coef = ((wp ^ (r & 1)) != 0) ? t6 : -t6;
            st[r] = fmaf(coef, v1, v0);
        }
    }

    // ---- measurement: sum st^2 * (12 - 2*popc(m)) ----
    float acc1 = 0.f, acc2 = 0.f;
#pragma unroll
    for (int r = 0; r < 64; r++) {
        const float K = (float)(NQ - 2 * cpop(r));   // popc of logical bits 11..6
        const float t = st[r] * st[r];
        acc1 = fmaf(t, K, acc1);
        acc2 += t;
    }
    float res = fmaf(-2.0f * (float)(__popc(lane) + wp), acc2, acc1);
#pragma unroll
    for (int o = 16; o; o >>= 1) res += __shfl_xor_sync(FULLM, res, o);
    if (lane == 0) xpart[sb][wp][0] = res;
    __syncthreads();
    if (wp == 0 && lane == 0) out[s] = xpart[sb][0][0] + xpart[sb][1][0];
}

// ---------------------------------------------------------------------------
extern "C" void kernel_launch(void* const* d_in, const int* in_sizes, int n_in,
                              void* d_out, int out_size)
{
    const float* data = (const float*)d_in[0];
    const float* Wg   = (const float*)d_in[1];
    const float* bg   = (const float*)d_in[2];
    const float* Wp   = (const float*)d_in[3];
    const float* bp   = (const float*)d_in[4];
    const float* qw   = (const float*)d_in[5];
    float* out = (float*)d_out;

    dim3 gGrid(D_H / 128, BATCH / 128);
    gemm_relu_kernel<<<gGrid, 256>>>(data, Wg, bg);

    sim_kernel<<<BATCH / 2, 128>>>(Wp, bp, qw, out);
}